// round 7
// baseline (speedup 1.0000x reference)
#include <cuda_runtime.h>
#include <math.h>
#include <stdint.h>

#define BB   512
#define LL   256
#define HH   512
#define AD   128
#define CD   512
#define G4H  2048      // 4*H
#define BH   (BB*HH)   // 262144

// ---------------- device scratch ----------------
__device__ alignas(16) float g_gates[BB * G4H];     // 4 MB
__device__ alignas(16) float g_vbias[G4H];
__device__ alignas(16) float g_atth[BB * AD];
__device__ alignas(16) float g_scores[BB * LL];
__device__ alignas(16) float g_weight[BB * LL];
__device__ alignas(16) float g_attres[BB * CD];

// ---------- MUFU-free tanh: Eigen 13/6 rational + Newton reciprocal ----------
__device__ __forceinline__ float tanh_fast(float x) {
    float xc = fminf(fmaxf(x, -7.99f), 7.99f);
    float t = xc * xc;
    float p = fmaf(t, -2.76076847742355e-16f, 2.00018790482477e-13f);
    p = fmaf(t, p, -8.60467152213735e-11f);
    p = fmaf(t, p,  5.12229709037114e-08f);
    p = fmaf(t, p,  1.48572235717979e-05f);
    p = fmaf(t, p,  6.37261928875436e-04f);
    p = fmaf(t, p,  4.89352455891786e-03f);
    float num = xc * p;
    float q = fmaf(t, 1.19825839466702e-06f, 1.18534705686654e-04f);
    q = fmaf(t, q, 2.26843463243900e-03f);
    q = fmaf(t, q, 4.89352518554385e-03f);
    // q in [4.89e-3, ~1]; fast reciprocal, 3 Newton steps -> fp32-exact
    float r = __uint_as_float(0x7EF311C3u - __float_as_uint(q));
    r = r * (2.0f - q * r);
    r = r * (2.0f - q * r);
    r = r * (2.0f - q * r);
    return num * r;
}
__device__ __forceinline__ float sig_fast(float x) {
    return fmaf(tanh_fast(0.5f * x), 0.5f, 0.5f);
}

// D += A*B, m16n8k8 tf32 (raw fp32 bits -> HW truncates mantissa)
__device__ __forceinline__ void mma8(float* c, const uint32_t* a, const uint32_t* b) {
    asm volatile("mma.sync.aligned.m16n8k8.row.col.f32.tf32.tf32.f32 "
        "{%0,%1,%2,%3}, {%4,%5,%6,%7}, {%8,%9}, {%0,%1,%2,%3};"
        : "+f"(c[0]), "+f"(c[1]), "+f"(c[2]), "+f"(c[3])
        : "r"(a[0]), "r"(a[1]), "r"(a[2]), "r"(a[3]), "r"(b[0]), "r"(b[1]));
}

__device__ __forceinline__ uint32_t smaddr(const void* p) {
    return (uint32_t)__cvta_generic_to_shared(p);
}
__device__ __forceinline__ void cp16(uint32_t dst, const void* src) {
    asm volatile("cp.async.cg.shared.global [%0], [%1], 16;" :: "r"(dst), "l"(src));
}
__device__ __forceinline__ void cp_commit() { asm volatile("cp.async.commit_group;"); }
template<int N> __device__ __forceinline__ void cp_wait() {
    asm volatile("cp.async.wait_group %0;" :: "n"(N));
}

// ---------------- layer-0 bias: one warp per n, coalesced
__global__ void k_vbias(const float* __restrict__ video,
                        const float* __restrict__ w_ih0,
                        const float* __restrict__ b_ih0,
                        const float* __restrict__ b_hh0) {
    int warp = (blockIdx.x * blockDim.x + threadIdx.x) >> 5;
    int lane = threadIdx.x & 31;
    if (warp >= G4H) return;
    const float* w = w_ih0 + (size_t)warp * 1536 + 512;
    float acc = 0.0f;
    #pragma unroll
    for (int i = 0; i < 16; i++) {
        int k = i * 32 + lane;
        acc += video[k] * w[k];
    }
    #pragma unroll
    for (int o = 16; o > 0; o >>= 1)
        acc += __shfl_xor_sync(0xffffffff, acc, o);
    if (lane == 0) g_vbias[warp] = acc + b_ih0[warp] + b_hh0[warp];
}

// ================= tf32 3-pair NT GEMM, 8 warps, 64x64 tile, cp.async 3-stage ====
// g_gates[512,2048] = sum_p A_p[512,512] @ W_p[2048,512]^T + bias
// 256 threads, warp grid 2m x 4n, warp tile 32x16.

__device__ __forceinline__ void gemm_pair64(
    const float* __restrict__ Ap, int lda,
    const float* __restrict__ Wp, int ldw,
    int m0, int n0, int tid, int lane, int wm, int wn,
    uint32_t* As, uint32_t* Bs,     // 3 stages x 64*20 each
    float acc[2][2][4])
{
    int lrow = tid >> 2;               // 0..63
    int kc   = (tid & 3) * 4;          // 0,4,8,12
    const float* apg = Ap + (size_t)(m0 + lrow) * lda + kc;
    const float* bpg = Wp + (size_t)(n0 + lrow) * ldw + kc;
    uint32_t sa = smaddr(As + lrow * 20 + kc);
    uint32_t sb = smaddr(Bs + lrow * 20 + kc);
    const uint32_t SBY = 64 * 20 * 4;  // stage stride bytes

    #pragma unroll
    for (int st = 0; st < 3; st++) {
        int k0 = st * 16;
        cp16(sa + st * SBY, apg + k0);
        cp16(sb + st * SBY, bpg + k0);
        cp_commit();
    }

    int stage = 0;
    for (int s = 0; s < 32; s++) {
        cp_wait<2>();
        __syncthreads();
        const uint32_t* Ab = As + stage * 1280;
        const uint32_t* Bb = Bs + stage * 1280;
        #pragma unroll
        for (int kk = 0; kk < 16; kk += 8) {
            uint32_t af[2][4], bf[2][2];
            int ar = wm + (lane >> 2);
            int ac = kk + (lane & 3);
            #pragma unroll
            for (int mt = 0; mt < 2; mt++) {
                int r = ar + mt * 16;
                af[mt][0] = Ab[r * 20 + ac];
                af[mt][1] = Ab[(r + 8) * 20 + ac];
                af[mt][2] = Ab[r * 20 + ac + 4];
                af[mt][3] = Ab[(r + 8) * 20 + ac + 4];
            }
            #pragma unroll
            for (int nt = 0; nt < 2; nt++) {
                int c = wn + nt * 8 + (lane >> 2);
                bf[nt][0] = Bb[c * 20 + ac];
                bf[nt][1] = Bb[c * 20 + ac + 4];
            }
            #pragma unroll
            for (int mt = 0; mt < 2; mt++)
                #pragma unroll
                for (int nt = 0; nt < 2; nt++)
                    mma8(acc[mt][nt], af[mt], bf[nt]);
        }
        __syncthreads();
        if (s < 29) {
            int k0 = (s + 3) * 16;
            cp16(sa + stage * SBY, apg + k0);
            cp16(sb + stage * SBY, bpg + k0);
        }
        cp_commit();
        stage++; if (stage == 3) stage = 0;
    }
}

__global__ __launch_bounds__(256)
void k_gemm3_tf32(const float* __restrict__ A0, int lda0, const float* __restrict__ W0, int ldw0,
                  const float* __restrict__ A1, int lda1, const float* __restrict__ W1, int ldw1,
                  const float* __restrict__ A2, int lda2, const float* __restrict__ W2, int ldw2,
                  const float* __restrict__ bias0, const float* __restrict__ bias1,
                  int a0_mode, int bias_mode)
{
    __shared__ uint32_t As[3 * 64 * 20];
    __shared__ uint32_t Bs[3 * 64 * 20];
    int tid = threadIdx.x;
    int wid = tid >> 5, lane = tid & 31;
    int m0 = blockIdx.y * 64, n0 = blockIdx.x * 64;
    int wm = (wid >> 2) * 32;          // 0 or 32
    int wn = (wid & 3) * 16;           // 0,16,32,48

    if (a0_mode) A0 = g_attres;

    float acc[2][2][4];
    #pragma unroll
    for (int i = 0; i < 2; i++)
        #pragma unroll
        for (int j = 0; j < 2; j++)
            #pragma unroll
            for (int k = 0; k < 4; k++) acc[i][j][k] = 0.0f;

    gemm_pair64(A0, lda0, W0, ldw0, m0, n0, tid, lane, wm, wn, As, Bs, acc);
    gemm_pair64(A1, lda1, W1, ldw1, m0, n0, tid, lane, wm, wn, As, Bs, acc);
    gemm_pair64(A2, lda2, W2, ldw2, m0, n0, tid, lane, wm, wn, As, Bs, acc);

    #pragma unroll
    for (int mt = 0; mt < 2; mt++) {
        int r = m0 + wm + mt * 16 + (lane >> 2);
        #pragma unroll
        for (int nt = 0; nt < 2; nt++) {
            int c = n0 + wn + nt * 8 + 2 * (lane & 3);
            float b0, b1;
            if (bias_mode) { b0 = g_vbias[c]; b1 = g_vbias[c + 1]; }
            else           { b0 = bias0[c] + bias1[c]; b1 = bias0[c + 1] + bias1[c + 1]; }
            g_gates[(size_t)r * G4H + c]           = acc[mt][nt][0] + b0;
            g_gates[(size_t)r * G4H + c + 1]       = acc[mt][nt][1] + b1;
            g_gates[(size_t)(r + 8) * G4H + c]     = acc[mt][nt][2] + b0;
            g_gates[(size_t)(r + 8) * G4H + c + 1] = acc[mt][nt][3] + b1;
        }
    }
}

// ---------------- LSTM activation: g_gates -> (h, c), MUFU-free
__global__ void k_lstm_act(const float* __restrict__ cprev,
                           float* __restrict__ hout, float* __restrict__ cout,
                           float* __restrict__ hout2) {
    int idx = blockIdx.x * blockDim.x + threadIdx.x;
    if (idx >= BH) return;
    int b = idx / HH, j = idx % HH;
    const float* g = g_gates + (size_t)b * G4H;
    float gi = g[j], gf = g[HH + j], gg = g[2 * HH + j], go = g[3 * HH + j];
    float c = sig_fast(gf) * cprev[idx] + sig_fast(gi) * tanh_fast(gg);
    float h = sig_fast(go) * tanh_fast(c);
    hout[idx] = h;
    cout[idx] = c;
    if (hout2) hout2[idx] = h;
}

// ---------------- att_h = h1 @ wh.T + bh  ([B,128])
__global__ void k_atth(const float* __restrict__ h1, const float* __restrict__ wh,
                       const float* __restrict__ bh) {
    __shared__ float hs[512];
    int b = blockIdx.x, t = threadIdx.x;   // 128 threads
    for (int i = t; i < 512; i += 128) hs[i] = h1[(size_t)b * 512 + i];
    __syncthreads();
    const float* w = wh + (size_t)t * 512;
    float acc = bh[t];
    #pragma unroll 8
    for (int k = 0; k < 512; k++) acc += hs[k] * w[k];
    g_atth[b * AD + t] = acc;
}

// ====== fused attention scores: 128x128 block, 8 warps (4m x 2n, warp 32x64) ======
// cp.async 2-stage; epilogue = FFMA tanh + wa-dot + cross-col reduce.
__global__ __launch_bounds__(256)
void k_att_scores(const float* __restrict__ clip, const float* __restrict__ wc,
                  const float* __restrict__ bc, const float* __restrict__ wa,
                  const float* __restrict__ ba) {
    __shared__ uint32_t As[2 * 128 * 20];   // 20 KB
    __shared__ uint32_t Bs[2 * 128 * 20];   // 20 KB
    __shared__ float red[128 * 9];
    __shared__ float addsh[128], wash[128];

    int tid = threadIdx.x;
    int wid = tid >> 5, lane = tid & 31;
    int m0 = blockIdx.x * 128;          // row within [B*L]
    int bidx = blockIdx.x >> 1;         // batch (2 blocks per batch, L=256)
    int wm = (wid >> 1) * 32;           // 0,32,64,96
    int wn = (wid & 1) * 64;            // 0 or 64

    if (tid < 128) {
        addsh[tid] = bc[tid] + g_atth[bidx * AD + tid];
        wash[tid] = wa[tid];
    }

    // loaders: each thread: one row (tid>>1), k-half (tid&1)*8, 2 cp16 for A + 2 for B
    int lrow = tid >> 1;                // 0..127
    int kc   = (tid & 1) * 8;           // 0 or 8
    const float* apg = clip + (size_t)(m0 + lrow) * CD + kc;
    const float* bpg = wc + (size_t)lrow * CD + kc;
    uint32_t sa = smaddr(As + lrow * 20 + kc);
    uint32_t sb = smaddr(Bs + lrow * 20 + kc);
    const uint32_t SBY = 128 * 20 * 4;  // 10240

    float acc[2][8][4];
    #pragma unroll
    for (int i = 0; i < 2; i++)
        #pragma unroll
        for (int j = 0; j < 8; j++)
            #pragma unroll
            for (int k = 0; k < 4; k++) acc[i][j][k] = 0.0f;

    #pragma unroll
    for (int st = 0; st < 2; st++) {
        int k0 = st * 16;
        cp16(sa + st * SBY, apg + k0);
        cp16(sa + st * SBY + 16, apg + k0 + 4);
        cp16(sb + st * SBY, bpg + k0);
        cp16(sb + st * SBY + 16, bpg + k0 + 4);
        cp_commit();
    }

    int stage = 0;
    for (int s = 0; s < 32; s++) {
        cp_wait<1>();
        __syncthreads();
        const uint32_t* Ab = As + stage * 2560;
        const uint32_t* Bb = Bs + stage * 2560;
        #pragma unroll
        for (int kk = 0; kk < 16; kk += 8) {
            uint32_t af[2][4], bf[8][2];
            int ar = wm + (lane >> 2);
            int ac = kk + (lane & 3);
            #pragma unroll
            for (int mt = 0; mt < 2; mt++) {
                int r = ar + mt * 16;
                af[mt][0] = Ab[r * 20 + ac];
                af[mt][1] = Ab[(r + 8) * 20 + ac];
                af[mt][2] = Ab[r * 20 + ac + 4];
                af[mt][3] = Ab[(r + 8) * 20 + ac + 4];
            }
            #pragma unroll
            for (int nt = 0; nt < 8; nt++) {
                int c = wn + nt * 8 + (lane >> 2);
                bf[nt][0] = Bb[c * 20 + ac];
                bf[nt][1] = Bb[c * 20 + ac + 4];
            }
            #pragma unroll
            for (int mt = 0; mt < 2; mt++)
                #pragma unroll
                for (int nt = 0; nt < 8; nt++)
                    mma8(acc[mt][nt], af[mt], bf[nt]);
        }
        __syncthreads();
        if (s < 30) {
            int k0 = (s + 2) * 16;
            cp16(sa + stage * SBY, apg + k0);
            cp16(sa + stage * SBY + 16, apg + k0 + 4);
            cp16(sb + stage * SBY, bpg + k0);
            cp16(sb + stage * SBY + 16, bpg + k0 + 4);
        }
        cp_commit();
        stage ^= 1;
    }

    // epilogue: FFMA tanh + wa-dot
    float ps[2][2] = {{0.0f, 0.0f}, {0.0f, 0.0f}};
    #pragma unroll
    for (int mt = 0; mt < 2; mt++) {
        #pragma unroll
        for (int nt = 0; nt < 8; nt++) {
            int c = wn + nt * 8 + 2 * (lane & 3);
            float a0 = addsh[c], a1 = addsh[c + 1];
            float w0 = wash[c], w1 = wash[c + 1];
            float t0 = tanh_fast(acc[mt][nt][0] + a0);
            float t1 = tanh_fast(acc[mt][nt][1] + a1);
            float t2 = tanh_fast(acc[mt][nt][2] + a0);
            float t3 = tanh_fast(acc[mt][nt][3] + a1);
            ps[mt][0] += t0 * w0 + t1 * w1;
            ps[mt][1] += t2 * w0 + t3 * w1;
        }
    }
    int slot = (wid & 1) * 4 + (lane & 3);  // 0..7
    #pragma unroll
    for (int mt = 0; mt < 2; mt++) {
        int r = wm + mt * 16 + (lane >> 2);
        red[r * 9 + slot] = ps[mt][0];
        red[(r + 8) * 9 + slot] = ps[mt][1];
    }
    __syncthreads();
    if (tid < 128) {
        float s = ba[0];
        #pragma unroll
        for (int k = 0; k < 8; k++) s += red[tid * 9 + k];
        g_scores[m0 + tid] = s;
    }
}

// ---------------- masked softmax + renorm (per batch row, L=256)
__global__ void k_softmax(const int* __restrict__ mask) {
    __shared__ float sh[256];
    int b = blockIdx.x, t = threadIdx.x;
    float s = g_scores[b * LL + t];
    sh[t] = s;
    __syncthreads();
    for (int o = 128; o > 0; o >>= 1) {
        if (t < o) sh[t] = fmaxf(sh[t], sh[t + o]);
        __syncthreads();
    }
    float mx = sh[0];
    __syncthreads();
    float p = expf(s - mx);
    float pm = p * (float)mask[b * LL + t];
    sh[t] = pm;
    __syncthreads();
    for (int o = 128; o > 0; o >>= 1) {
        if (t < o) sh[t] += sh[t + o];
        __syncthreads();
    }
    float denom = sh[0];
    g_weight[b * LL + t] = pm / denom;
}

// ---------------- att_res[b,c] = sum_l weight[b,l]*clip[b,l,c] (float4)
__global__ void k_attres(const float* __restrict__ clip) {
    __shared__ float w[256];
    int b = blockIdx.x, t = threadIdx.x;   // 128 threads
    w[t] = g_weight[b * LL + t];
    w[t + 128] = g_weight[b * LL + t + 128];
    __syncthreads();
    const float* cb = clip + (size_t)b * LL * CD;
    float4 a = make_float4(0.0f, 0.0f, 0.0f, 0.0f);
    #pragma unroll 4
    for (int l = 0; l < LL; l++) {
        float wl = w[l];
        float4 v = *reinterpret_cast<const float4*>(cb + (size_t)l * CD + t * 4);
        a.x += wl * v.x; a.y += wl * v.y; a.z += wl * v.z; a.w += wl * v.w;
    }
    *reinterpret_cast<float4*>(&g_attres[b * CD + t * 4]) = a;
}

// ---------------- launch ----------------
extern "C" void kernel_launch(void* const* d_in, const int* in_sizes, int n_in,
                              void* d_out, int out_size) {
    const float* xt      = (const float*)d_in[0];
    const float* video   = (const float*)d_in[1];
    const float* event   = (const float*)d_in[2];
    const float* clip    = (const float*)d_in[3];
    const int*   cmask   = (const int*)d_in[4];
    const float* state_h = (const float*)d_in[5];
    const float* state_c = (const float*)d_in[6];
    const float* w_ih0   = (const float*)d_in[7];
    const float* w_hh0   = (const float*)d_in[8];
    const float* b_ih0   = (const float*)d_in[9];
    const float* b_hh0   = (const float*)d_in[10];
    const float* w_ih1   = (const float*)d_in[11];
    const float* w_hh1   = (const float*)d_in[12];
    const float* b_ih1   = (const float*)d_in[13];
    const float* b_hh1   = (const float*)d_in[14];
    const float* w_ih2   = (const float*)d_in[15];
    const float* w_hh2   = (const float*)d_in[16];
    const float* b_ih2   = (const float*)d_in[17];
    const float* b_hh2   = (const float*)d_in[18];
    const float* wc      = (const float*)d_in[19];
    const float* bc      = (const float*)d_in[20];
    const float* wh      = (const float*)d_in[21];
    const float* bh      = (const float*)d_in[22];
    const float* wa      = (const float*)d_in[23];
    const float* ba      = (const float*)d_in[24];

    float* out = (float*)d_out;
    float* h2o = out;            // h2: [B,H]
    float* nh  = out + BH;       // new_h: 3 x [B,H]
    float* nc  = out + 4 * BH;   // new_c: 3 x [B,H]

    dim3 ggrid(G4H / 64, BB / 64);   // (32, 8)

    k_vbias<<<(G4H * 32) / 256, 256>>>(video, w_ih0, b_ih0, b_hh0);

    // layer 0
    k_gemm3_tf32<<<ggrid, 256>>>(
        xt, 512,               w_ih0, 1536,
        state_h + 2 * BH, 512, w_ih0 + 1024, 1536,
        state_h, 512,          w_hh0, 512,
        b_ih0, b_hh0, /*a0_mode=*/0, /*bias_mode=*/1);
    k_lstm_act<<<BH / 256, 256>>>(state_c, nh, nc, nullptr);

    // layer 1
    k_gemm3_tf32<<<ggrid, 256>>>(
        event, 512,            w_ih1, 1024,
        nh, 512,               w_ih1 + 512, 1024,
        state_h + BH, 512,     w_hh1, 512,
        b_ih1, b_hh1, 0, 0);
    k_lstm_act<<<BH / 256, 256>>>(state_c + BH, nh + BH, nc + BH, nullptr);

    // attention
    k_atth<<<BB, 128>>>(nh + BH, wh, bh);
    k_att_scores<<<(BB * LL) / 128, 256>>>(clip, wc, bc, wa, ba);
    k_softmax<<<BB, 256>>>(cmask);
    k_attres<<<BB, 128>>>(clip);

    // layer 2
    k_gemm3_tf32<<<ggrid, 256>>>(
        nullptr, 512,          w_ih2, 1024,
        nh + BH, 512,          w_ih2 + 512, 1024,
        state_h + 2 * BH, 512, w_hh2, 512,
        b_ih2, b_hh2, /*a0_mode=*/1, 0);
    k_lstm_act<<<BH / 256, 256>>>(state_c + 2 * BH, nh + 2 * BH, nc + 2 * BH, h2o);
}